// round 2
// baseline (speedup 1.0000x reference)
#include <cuda_runtime.h>
#include <math.h>

// Problem constants (fixed by reference)
#define GN   100000      // nodes
#define GF   256         // in features
#define GO   64          // out features (H*C)
#define GH   8           // heads
#define GE   1600000     // edges
#define GTOT (GE + GN)   // edges + self loops
#define NEG_SLOPE 0.2f

// ---------------- static device scratch (no allocations allowed) -------------
__device__ float g_h[GN * GO];        // projected features [N,64]
__device__ float g_asrc[GN * GH];     // per-node src attention term [N,8]
__device__ float g_adst[GN * GH];     // per-node dst attention term [N,8]
__device__ int   g_count[GN];         // degree counter -> CSR cursor -> row end
__device__ int   g_rowptr[GN];        // CSR row start (by dst)
__device__ int   g_srclist[GTOT];     // CSR: src node ids grouped by dst
__device__ int   g_bsum[128];         // scan block sums
__device__ int   g_boff[128];         // scan block offsets
__device__ int   g_is64;              // 1 if edge_index is int64, 0 if int32

// ---------------- K0: detect edge_index dtype --------------------------------
// If the buffer is int32, interpreting pairs as int64 gives values with a
// nonzero high word almost surely (P[hi==0] = N/2^32 per element). 64 probes
// make misdetection impossible in practice. Deterministic, capture-safe.
__global__ void dtype_kernel(const void* ei) {
    if (threadIdx.x != 0 || blockIdx.x != 0) return;
    const long long* p = (const long long*)ei;
    int ok64 = 1;
    for (int i = 0; i < 64; i++) {
        long long v = p[i];
        if (v < 0 || v >= GN) { ok64 = 0; break; }
    }
    g_is64 = ok64;
}

__device__ __forceinline__ int edge_at(const void* ei, long long idx) {
    if (g_is64) return (int)((const long long*)ei)[idx];
    return ((const int*)ei)[idx];
}

// ---------------- K1: GEMM  h = x @ W^T   (M=100000, N=64, K=256) ------------
#define BM 128
#define BK 32
__global__ void gemm_kernel(const float* __restrict__ x,
                            const float* __restrict__ W) {
    __shared__ float As[BK][132];   // 132*4=528B rows: 16B-aligned, conflict-free
    __shared__ float Bs[BK][68];

    const int tid = threadIdx.x;          // 256 threads
    const int m_block = blockIdx.x * BM;
    const int tn = tid & 15;              // 16 threads along N
    const int tm = tid >> 4;              // 16 threads along M
    const int m0 = tm * 8;
    const int n0 = tn * 4;

    float acc[8][4];
#pragma unroll
    for (int i = 0; i < 8; i++)
#pragma unroll
        for (int j = 0; j < 4; j++) acc[i][j] = 0.f;

    for (int k0 = 0; k0 < GF; k0 += BK) {
        // Load A tile 128x32 (4 float4 per thread), store transposed
#pragma unroll
        for (int i = 0; i < 4; i++) {
            int f   = tid + i * 256;
            int row = f >> 3;
            int k4  = (f & 7) << 2;
            int gm  = m_block + row;
            float4 v = make_float4(0.f, 0.f, 0.f, 0.f);
            if (gm < GN) v = *(const float4*)(x + (size_t)gm * GF + k0 + k4);
            As[k4 + 0][row] = v.x; As[k4 + 1][row] = v.y;
            As[k4 + 2][row] = v.z; As[k4 + 3][row] = v.w;
        }
        // Load B tile: Bs[k][j] = W[j*256 + k0+k]  (2 float4 per thread)
#pragma unroll
        for (int i = 0; i < 2; i++) {
            int f  = tid + i * 256;
            int n  = f >> 3;
            int k4 = (f & 7) << 2;
            float4 v = *(const float4*)(W + n * GF + k0 + k4);
            Bs[k4 + 0][n] = v.x; Bs[k4 + 1][n] = v.y;
            Bs[k4 + 2][n] = v.z; Bs[k4 + 3][n] = v.w;
        }
        __syncthreads();
#pragma unroll
        for (int k = 0; k < BK; k++) {
            float4 a0 = *(const float4*)&As[k][m0];
            float4 a1 = *(const float4*)&As[k][m0 + 4];
            float4 b  = *(const float4*)&Bs[k][n0];
            float a[8] = {a0.x, a0.y, a0.z, a0.w, a1.x, a1.y, a1.z, a1.w};
            float bb[4] = {b.x, b.y, b.z, b.w};
#pragma unroll
            for (int i = 0; i < 8; i++)
#pragma unroll
                for (int j = 0; j < 4; j++) acc[i][j] += a[i] * bb[j];
        }
        __syncthreads();
    }
#pragma unroll
    for (int i = 0; i < 8; i++) {
        int gm = m_block + m0 + i;
        if (gm < GN) {
            float4 v = make_float4(acc[i][0], acc[i][1], acc[i][2], acc[i][3]);
            *(float4*)(g_h + (size_t)gm * GO + n0) = v;
        }
    }
}

// ---------------- K2: per-node attention terms + zero counters ---------------
__global__ void attn_kernel(const float* __restrict__ att_src,
                            const float* __restrict__ att_dst) {
    int i = blockIdx.x * blockDim.x + threadIdx.x;
    if (i < GN) g_count[i] = 0;
    if (i >= GN * GH) return;
    int n = i >> 3, h = i & 7;
    const float4* hp = (const float4*)(g_h + (size_t)n * GO + h * 8);
    float4 v0 = hp[0], v1 = hp[1];
    const float4* as = (const float4*)(att_src + h * 8);
    const float4* ad = (const float4*)(att_dst + h * 8);
    float4 s0 = as[0], s1 = as[1];
    float4 d0 = ad[0], d1 = ad[1];
    float rs = v0.x * s0.x + v0.y * s0.y + v0.z * s0.z + v0.w * s0.w +
               v1.x * s1.x + v1.y * s1.y + v1.z * s1.z + v1.w * s1.w;
    float rd = v0.x * d0.x + v0.y * d0.y + v0.z * d0.z + v0.w * d0.w +
               v1.x * d1.x + v1.y * d1.y + v1.z * d1.z + v1.w * d1.w;
    g_asrc[i] = rs;
    g_adst[i] = rd;
}

// ---------------- K3: count incoming edges per dst ---------------------------
__global__ void count_kernel(const void* __restrict__ ei) {
    int i = blockIdx.x * blockDim.x + threadIdx.x;
    if (i >= GTOT) return;
    int d = (i < GE) ? edge_at(ei, (long long)GE + i) : (i - GE);
    if ((unsigned)d < (unsigned)GN)          // never trap on bad input
        atomicAdd(&g_count[d], 1);
}

// ---------------- K4a/b/c: exclusive scan of counts -> rowptr ----------------
__global__ void scanA_kernel() {
    __shared__ int sh[1024];
    int t = threadIdx.x;
    int n = blockIdx.x * 1024 + t;
    sh[t] = (n < GN) ? g_count[n] : 0;
    __syncthreads();
    for (int off = 512; off > 0; off >>= 1) {
        if (t < off) sh[t] += sh[t + off];
        __syncthreads();
    }
    if (t == 0) g_bsum[blockIdx.x] = sh[0];
}
__global__ void scanB_kernel(int nb) {
    if (threadIdx.x == 0 && blockIdx.x == 0) {
        int run = 0;
        for (int b = 0; b < nb; b++) { g_boff[b] = run; run += g_bsum[b]; }
    }
}
__global__ void scanC_kernel() {
    __shared__ int sh[1024];
    int t = threadIdx.x;
    int n = blockIdx.x * 1024 + t;
    int v = (n < GN) ? g_count[n] : 0;
    sh[t] = v;
    __syncthreads();
    for (int off = 1; off < 1024; off <<= 1) {
        int x = (t >= off) ? sh[t - off] : 0;
        __syncthreads();
        sh[t] += x;
        __syncthreads();
    }
    if (n < GN) {
        int ex = sh[t] - v + g_boff[blockIdx.x];  // exclusive prefix
        g_rowptr[n] = ex;
        g_count[n]  = ex;  // becomes the fill cursor; ends as row end
    }
}

// ---------------- K5: fill CSR src lists -------------------------------------
__global__ void fill_kernel(const void* __restrict__ ei) {
    int i = blockIdx.x * blockDim.x + threadIdx.x;
    if (i >= GTOT) return;
    int s, d;
    if (i < GE) { s = edge_at(ei, i); d = edge_at(ei, (long long)GE + i); }
    else        { s = d = i - GE; }
    if ((unsigned)d >= (unsigned)GN || (unsigned)s >= (unsigned)GN) return;
    int pos = atomicAdd(&g_count[d], 1);
    if ((unsigned)pos < (unsigned)GTOT) g_srclist[pos] = s;
}

// ---------------- K6: warp-per-dst gather: softmax + aggregate + log_softmax -
__global__ void gather_kernel(const float* __restrict__ bias,
                              float* __restrict__ out) {
    __shared__ float s_m[8][8];   // [warp][head] max
    __shared__ float s_i[8][8];   // [warp][head] 1/sum
    const int wid  = threadIdx.x >> 5;
    const int lane = threadIdx.x & 31;
    const int n    = blockIdx.x * 8 + wid;
    if (n >= GN) return;

    const int start = g_rowptr[n];
    const int end   = g_count[n];

    float ad[8];
    {
        const float4* p = (const float4*)(g_adst + n * GH);
        float4 u0 = p[0], u1 = p[1];
        ad[0]=u0.x; ad[1]=u0.y; ad[2]=u0.z; ad[3]=u0.w;
        ad[4]=u1.x; ad[5]=u1.y; ad[6]=u1.z; ad[7]=u1.w;
    }

    // ---- pass A: per-head max of leaky(a_src[s]+a_dst[n]) ----
    float mx[8];
#pragma unroll
    for (int h = 0; h < 8; h++) mx[h] = -1e30f;
    for (int i = start + lane; i < end; i += 32) {
        int s = g_srclist[i];
        const float4* p = (const float4*)(g_asrc + s * GH);
        float4 u0 = p[0], u1 = p[1];
        float av[8] = {u0.x,u0.y,u0.z,u0.w,u1.x,u1.y,u1.z,u1.w};
#pragma unroll
        for (int h = 0; h < 8; h++) {
            float v = av[h] + ad[h];
            v = v > 0.f ? v : NEG_SLOPE * v;
            mx[h] = fmaxf(mx[h], v);
        }
    }
#pragma unroll
    for (int h = 0; h < 8; h++)
#pragma unroll
        for (int off = 16; off > 0; off >>= 1)
            mx[h] = fmaxf(mx[h], __shfl_xor_sync(0xffffffffu, mx[h], off));

    // ---- pass B: per-head sum of exp ----
    float sm[8];
#pragma unroll
    for (int h = 0; h < 8; h++) sm[h] = 0.f;
    for (int i = start + lane; i < end; i += 32) {
        int s = g_srclist[i];
        const float4* p = (const float4*)(g_asrc + s * GH);
        float4 u0 = p[0], u1 = p[1];
        float av[8] = {u0.x,u0.y,u0.z,u0.w,u1.x,u1.y,u1.z,u1.w};
#pragma unroll
        for (int h = 0; h < 8; h++) {
            float v = av[h] + ad[h];
            v = v > 0.f ? v : NEG_SLOPE * v;
            sm[h] += expf(v - mx[h]);
        }
    }
#pragma unroll
    for (int h = 0; h < 8; h++)
#pragma unroll
        for (int off = 16; off > 0; off >>= 1)
            sm[h] += __shfl_xor_sync(0xffffffffu, sm[h], off);

    if (lane == 0) {
#pragma unroll
        for (int h = 0; h < 8; h++) {
            s_m[wid][h] = mx[h];
            s_i[wid][h] = 1.f / (sm[h] + 1e-16f);
        }
    }
    __syncwarp();

    // ---- pass C: lanes = output components; accumulate messages ----
    const int c0 = lane, c1 = lane + 32;
    const int h0 = lane >> 3, h1 = h0 + 4;
    const float mxa = s_m[wid][h0], mxb = s_m[wid][h1];
    const float iva = s_i[wid][h0], ivb = s_i[wid][h1];
    const float ada = g_adst[n * GH + h0];
    const float adb = g_adst[n * GH + h1];

    float acc0 = 0.f, acc1 = 0.f;
    for (int i = start; i < end; i++) {
        int s = g_srclist[i];
        float va = g_asrc[s * GH + h0] + ada;
        va = va > 0.f ? va : NEG_SLOPE * va;
        float vb = g_asrc[s * GH + h1] + adb;
        vb = vb > 0.f ? vb : NEG_SLOPE * vb;
        float a0 = expf(va - mxa) * iva;
        float a1 = expf(vb - mxb) * ivb;
        acc0 += a0 * g_h[(size_t)s * GO + c0];
        acc1 += a1 * g_h[(size_t)s * GO + c1];
    }
    acc0 += bias[c0];
    acc1 += bias[c1];

    // ---- log_softmax over 64 components of this node ----
    float vmax = fmaxf(acc0, acc1);
#pragma unroll
    for (int off = 16; off > 0; off >>= 1)
        vmax = fmaxf(vmax, __shfl_xor_sync(0xffffffffu, vmax, off));
    float se = expf(acc0 - vmax) + expf(acc1 - vmax);
#pragma unroll
    for (int off = 16; off > 0; off >>= 1)
        se += __shfl_xor_sync(0xffffffffu, se, off);
    float lg = vmax + logf(se);

    out[(size_t)n * GO + c0] = acc0 - lg;
    out[(size_t)n * GO + c1] = acc1 - lg;
}

// ---------------- launcher ---------------------------------------------------
extern "C" void kernel_launch(void* const* d_in, const int* in_sizes, int n_in,
                              void* d_out, int out_size) {
    const float* x       = (const float*)d_in[0];
    const void*  eidx    = d_in[1];                 // int32 or int64, probed on device
    const float* W       = (const float*)d_in[2];
    const float* att_src = (const float*)d_in[3];
    const float* att_dst = (const float*)d_in[4];
    const float* bias    = (const float*)d_in[5];
    float*       out     = (float*)d_out;

    // K0: edge dtype probe
    dtype_kernel<<<1, 32>>>(eidx);

    // K1: projection GEMM
    gemm_kernel<<<(GN + BM - 1) / BM, 256>>>(x, W);

    // K2: per-node attention terms (+ zero degree counters)
    attn_kernel<<<(GN * GH + 255) / 256, 256>>>(att_src, att_dst);

    // K3..K5: build dst-CSR
    count_kernel<<<(GTOT + 255) / 256, 256>>>(eidx);
    const int NB = (GN + 1023) / 1024;   // 98
    scanA_kernel<<<NB, 1024>>>();
    scanB_kernel<<<1, 32>>>(NB);
    scanC_kernel<<<NB, 1024>>>();
    fill_kernel<<<(GTOT + 255) / 256, 256>>>(eidx);

    // K6: fused softmax + aggregation + log_softmax, one warp per dst node
    gather_kernel<<<(GN * 32 + 255) / 256, 256>>>(bias, out);
}

// round 3
// speedup vs baseline: 1.0715x; 1.0715x over previous
#include <cuda_runtime.h>
#include <math.h>

// Problem constants (fixed by reference)
#define GN   100000      // nodes
#define GF   256         // in features
#define GO   64          // out features (H*C)
#define GH   8           // heads
#define GE   1600000     // edges
#define GTOT (GE + GN)   // edges + self loops
#define NEG_SLOPE 0.2f

// ---------------- static device scratch (no allocations allowed) -------------
__device__ float g_h[GN * GO];        // projected features [N,64]
__device__ float g_asrc[GN * GH];     // per-node src attention term [N,8]
__device__ float g_adst[GN * GH];     // per-node dst attention term [N,8]
__device__ int   g_count[GN];         // degree counter -> CSR cursor -> row end
__device__ int   g_rowptr[GN];        // CSR row start (by dst)
__device__ int   g_srclist[GTOT];     // CSR: src node ids grouped by dst
__device__ int   g_bsum[128];         // scan block sums
__device__ int   g_is64;              // 1 if edge_index is int64, 0 if int32

// ---------------- K0: detect edge_index dtype --------------------------------
__global__ void dtype_kernel(const void* ei) {
    if (threadIdx.x != 0 || blockIdx.x != 0) return;
    const long long* p = (const long long*)ei;
    int ok64 = 1;
    for (int i = 0; i < 64; i++) {
        long long v = p[i];
        if (v < 0 || v >= GN) { ok64 = 0; break; }
    }
    g_is64 = ok64;
}

__device__ __forceinline__ int edge_at(const void* ei, long long idx) {
    if (g_is64) return (int)((const long long*)ei)[idx];
    return ((const int*)ei)[idx];
}

// ---------------- K1: GEMM  h = x @ W^T  (M=100000, N=64, K=256) -------------
// 128 threads, per-thread 8x8 tile: 64B LDS per 64 FFMA -> crossbar-balanced.
#define BM 128
#define BN 64
#define BK 16
__global__ void __launch_bounds__(128) gemm_kernel(const float* __restrict__ x,
                                                   const float* __restrict__ W) {
    __shared__ float As[BK][BM + 4];
    __shared__ float Bs[BK][BN + 4];

    const int tid = threadIdx.x;          // 128 threads
    const int m_block = blockIdx.x * BM;
    const int tm = tid >> 3;              // 16 threads along M
    const int tn = tid & 7;               // 8 threads along N
    const int m0 = tm * 8;
    const int n0 = tn * 8;

    float acc[8][8];
#pragma unroll
    for (int i = 0; i < 8; i++)
#pragma unroll
        for (int j = 0; j < 8; j++) acc[i][j] = 0.f;

    for (int k0 = 0; k0 < GF; k0 += BK) {
        // A tile 128x16: 512 float4 slots, 4 per thread, stored transposed
#pragma unroll
        for (int i = 0; i < 4; i++) {
            int f   = tid + i * 128;
            int row = f >> 2;
            int k4  = (f & 3) << 2;
            int gm  = m_block + row;
            float4 v = make_float4(0.f, 0.f, 0.f, 0.f);
            if (gm < GN) v = *(const float4*)(x + (size_t)gm * GF + k0 + k4);
            As[k4 + 0][row] = v.x; As[k4 + 1][row] = v.y;
            As[k4 + 2][row] = v.z; As[k4 + 3][row] = v.w;
        }
        // B tile 64x16: 256 float4 slots, 2 per thread
#pragma unroll
        for (int i = 0; i < 2; i++) {
            int f  = tid + i * 128;
            int n  = f >> 2;
            int k4 = (f & 3) << 2;
            float4 v = *(const float4*)(W + n * GF + k0 + k4);
            Bs[k4 + 0][n] = v.x; Bs[k4 + 1][n] = v.y;
            Bs[k4 + 2][n] = v.z; Bs[k4 + 3][n] = v.w;
        }
        __syncthreads();
#pragma unroll
        for (int k = 0; k < BK; k++) {
            float a[8], b[8];
            *(float4*)&a[0] = *(const float4*)&As[k][m0];
            *(float4*)&a[4] = *(const float4*)&As[k][m0 + 4];
            *(float4*)&b[0] = *(const float4*)&Bs[k][n0];
            *(float4*)&b[4] = *(const float4*)&Bs[k][n0 + 4];
#pragma unroll
            for (int i = 0; i < 8; i++)
#pragma unroll
                for (int j = 0; j < 8; j++) acc[i][j] += a[i] * b[j];
        }
        __syncthreads();
    }
#pragma unroll
    for (int i = 0; i < 8; i++) {
        int gm = m_block + m0 + i;
        if (gm < GN) {
            *(float4*)(g_h + (size_t)gm * GO + n0)     =
                make_float4(acc[i][0], acc[i][1], acc[i][2], acc[i][3]);
            *(float4*)(g_h + (size_t)gm * GO + n0 + 4) =
                make_float4(acc[i][4], acc[i][5], acc[i][6], acc[i][7]);
        }
    }
}

// ---------------- K2: per-node attention terms + zero counters ---------------
__global__ void attn_kernel(const float* __restrict__ att_src,
                            const float* __restrict__ att_dst) {
    int i = blockIdx.x * blockDim.x + threadIdx.x;
    if (i < GN) g_count[i] = 0;
    if (i >= GN * GH) return;
    int n = i >> 3, h = i & 7;
    const float4* hp = (const float4*)(g_h + (size_t)n * GO + h * 8);
    float4 v0 = hp[0], v1 = hp[1];
    const float4* as = (const float4*)(att_src + h * 8);
    const float4* ad = (const float4*)(att_dst + h * 8);
    float4 s0 = as[0], s1 = as[1];
    float4 d0 = ad[0], d1 = ad[1];
    float rs = v0.x * s0.x + v0.y * s0.y + v0.z * s0.z + v0.w * s0.w +
               v1.x * s1.x + v1.y * s1.y + v1.z * s1.z + v1.w * s1.w;
    float rd = v0.x * d0.x + v0.y * d0.y + v0.z * d0.z + v0.w * d0.w +
               v1.x * d1.x + v1.y * d1.y + v1.z * d1.z + v1.w * d1.w;
    g_asrc[i] = rs;
    g_adst[i] = rd;
}

// ---------------- K3: count incoming edges per dst ---------------------------
__global__ void count_kernel(const void* __restrict__ ei) {
    int i = blockIdx.x * blockDim.x + threadIdx.x;
    if (i >= GTOT) return;
    int d = (i < GE) ? edge_at(ei, (long long)GE + i) : (i - GE);
    if ((unsigned)d < (unsigned)GN)
        atomicAdd(&g_count[d], 1);
}

// ---------------- K4a/b: scan of counts -> rowptr ----------------------------
__global__ void scanA_kernel() {
    __shared__ int sh[1024];
    int t = threadIdx.x;
    int n = blockIdx.x * 1024 + t;
    sh[t] = (n < GN) ? g_count[n] : 0;
    __syncthreads();
    for (int off = 512; off > 0; off >>= 1) {
        if (t < off) sh[t] += sh[t + off];
        __syncthreads();
    }
    if (t == 0) g_bsum[blockIdx.x] = sh[0];
}
__global__ void scanC_kernel() {
    __shared__ int sh[1024];
    __shared__ int s_off;
    int t = threadIdx.x;
    // block offset = sum of prior block sums (<=128 values, cheap per-block redo)
    sh[t] = (t < 128 && t < blockIdx.x) ? g_bsum[t] : 0;
    __syncthreads();
    for (int off = 512; off > 0; off >>= 1) {
        if (t < off) sh[t] += sh[t + off];
        __syncthreads();
    }
    if (t == 0) s_off = sh[0];
    __syncthreads();

    int n = blockIdx.x * 1024 + t;
    int v = (n < GN) ? g_count[n] : 0;
    sh[t] = v;
    __syncthreads();
    for (int off = 1; off < 1024; off <<= 1) {
        int x = (t >= off) ? sh[t - off] : 0;
        __syncthreads();
        sh[t] += x;
        __syncthreads();
    }
    if (n < GN) {
        int ex = sh[t] - v + s_off;   // exclusive prefix
        g_rowptr[n] = ex;
        g_count[n]  = ex;             // becomes fill cursor; ends as row end
    }
}

// ---------------- K5: fill CSR src lists -------------------------------------
__global__ void fill_kernel(const void* __restrict__ ei) {
    int i = blockIdx.x * blockDim.x + threadIdx.x;
    if (i >= GTOT) return;
    int s, d;
    if (i < GE) { s = edge_at(ei, i); d = edge_at(ei, (long long)GE + i); }
    else        { s = d = i - GE; }
    if ((unsigned)d >= (unsigned)GN || (unsigned)s >= (unsigned)GN) return;
    int pos = atomicAdd(&g_count[d], 1);
    if ((unsigned)pos < (unsigned)GTOT) g_srclist[pos] = s;
}

// ---------------- K6: warp-per-dst gather: softmax + aggregate + log_softmax -
__global__ void gather_kernel(const float* __restrict__ bias,
                              float* __restrict__ out) {
    __shared__ float s_m[8][8];   // [warp][head] max
    __shared__ float s_i[8][8];   // [warp][head] 1/sum
    const int wid  = threadIdx.x >> 5;
    const int lane = threadIdx.x & 31;
    const int n    = blockIdx.x * 8 + wid;
    if (n >= GN) return;

    const int start = g_rowptr[n];
    const int end   = g_count[n];

    float ad[8];
    {
        const float4* p = (const float4*)(g_adst + n * GH);
        float4 u0 = p[0], u1 = p[1];
        ad[0]=u0.x; ad[1]=u0.y; ad[2]=u0.z; ad[3]=u0.w;
        ad[4]=u1.x; ad[5]=u1.y; ad[6]=u1.z; ad[7]=u1.w;
    }

    // ---- pass A: per-head max of leaky(a_src[s]+a_dst[n]) ----
    float mx[8];
#pragma unroll
    for (int h = 0; h < 8; h++) mx[h] = -1e30f;
    for (int i = start + lane; i < end; i += 32) {
        int s = g_srclist[i];
        const float4* p = (const float4*)(g_asrc + s * GH);
        float4 u0 = p[0], u1 = p[1];
        float av[8] = {u0.x,u0.y,u0.z,u0.w,u1.x,u1.y,u1.z,u1.w};
#pragma unroll
        for (int h = 0; h < 8; h++) {
            float v = av[h] + ad[h];
            v = v > 0.f ? v : NEG_SLOPE * v;
            mx[h] = fmaxf(mx[h], v);
        }
    }
#pragma unroll
    for (int h = 0; h < 8; h++)
#pragma unroll
        for (int off = 16; off > 0; off >>= 1)
            mx[h] = fmaxf(mx[h], __shfl_xor_sync(0xffffffffu, mx[h], off));

    // ---- pass B: per-head sum of exp ----
    float sm[8];
#pragma unroll
    for (int h = 0; h < 8; h++) sm[h] = 0.f;
    for (int i = start + lane; i < end; i += 32) {
        int s = g_srclist[i];
        const float4* p = (const float4*)(g_asrc + s * GH);
        float4 u0 = p[0], u1 = p[1];
        float av[8] = {u0.x,u0.y,u0.z,u0.w,u1.x,u1.y,u1.z,u1.w};
#pragma unroll
        for (int h = 0; h < 8; h++) {
            float v = av[h] + ad[h];
            v = v > 0.f ? v : NEG_SLOPE * v;
            sm[h] += __expf(v - mx[h]);
        }
    }
#pragma unroll
    for (int h = 0; h < 8; h++)
#pragma unroll
        for (int off = 16; off > 0; off >>= 1)
            sm[h] += __shfl_xor_sync(0xffffffffu, sm[h], off);

    if (lane == 0) {
#pragma unroll
        for (int h = 0; h < 8; h++) {
            s_m[wid][h] = mx[h];
            s_i[wid][h] = 1.f / (sm[h] + 1e-16f);
        }
    }
    __syncwarp();

    // ---- pass C: lanes = output components; accumulate messages ----
    const int c0 = lane, c1 = lane + 32;
    const int h0 = lane >> 3, h1 = h0 + 4;
    const float mxa = s_m[wid][h0], mxb = s_m[wid][h1];
    const float iva = s_i[wid][h0], ivb = s_i[wid][h1];
    const float ada = g_adst[n * GH + h0];
    const float adb = g_adst[n * GH + h1];

    float acc0 = 0.f, acc1 = 0.f;
    int i = start;
    for (; i + 4 <= end; i += 4) {
        // batch the index loads so the 4 dependent chains overlap
        int s0 = g_srclist[i],     s1 = g_srclist[i + 1];
        int s2 = g_srclist[i + 2], s3 = g_srclist[i + 3];
#pragma unroll
        for (int u = 0; u < 4; u++) {
            int s = (u == 0) ? s0 : (u == 1) ? s1 : (u == 2) ? s2 : s3;
            float va = g_asrc[s * GH + h0] + ada;
            va = va > 0.f ? va : NEG_SLOPE * va;
            float vb = g_asrc[s * GH + h1] + adb;
            vb = vb > 0.f ? vb : NEG_SLOPE * vb;
            float a0 = __expf(va - mxa) * iva;
            float a1 = __expf(vb - mxb) * ivb;
            acc0 += a0 * g_h[(size_t)s * GO + c0];
            acc1 += a1 * g_h[(size_t)s * GO + c1];
        }
    }
    for (; i < end; i++) {
        int s = g_srclist[i];
        float va = g_asrc[s * GH + h0] + ada;
        va = va > 0.f ? va : NEG_SLOPE * va;
        float vb = g_asrc[s * GH + h1] + adb;
        vb = vb > 0.f ? vb : NEG_SLOPE * vb;
        float a0 = __expf(va - mxa) * iva;
        float a1 = __expf(vb - mxb) * ivb;
        acc0 += a0 * g_h[(size_t)s * GO + c0];
        acc1 += a1 * g_h[(size_t)s * GO + c1];
    }
    acc0 += bias[c0];
    acc1 += bias[c1];

    // ---- log_softmax over 64 components of this node ----
    float vmax = fmaxf(acc0, acc1);
#pragma unroll
    for (int off = 16; off > 0; off >>= 1)
        vmax = fmaxf(vmax, __shfl_xor_sync(0xffffffffu, vmax, off));
    float se = __expf(acc0 - vmax) + __expf(acc1 - vmax);
#pragma unroll
    for (int off = 16; off > 0; off >>= 1)
        se += __shfl_xor_sync(0xffffffffu, se, off);
    float lg = vmax + __logf(se);

    out[(size_t)n * GO + c0] = acc0 - lg;
    out[(size_t)n * GO + c1] = acc1 - lg;
}

// ---------------- launcher ---------------------------------------------------
extern "C" void kernel_launch(void* const* d_in, const int* in_sizes, int n_in,
                              void* d_out, int out_size) {
    const float* x       = (const float*)d_in[0];
    const void*  eidx    = d_in[1];                 // int32 or int64, probed on device
    const float* W       = (const float*)d_in[2];
    const float* att_src = (const float*)d_in[3];
    const float* att_dst = (const float*)d_in[4];
    const float* bias    = (const float*)d_in[5];
    float*       out     = (float*)d_out;

    // K0: edge dtype probe
    dtype_kernel<<<1, 32>>>(eidx);

    // K1: projection GEMM
    gemm_kernel<<<(GN + BM - 1) / BM, 128>>>(x, W);

    // K2: per-node attention terms (+ zero degree counters)
    attn_kernel<<<(GN * GH + 255) / 256, 256>>>(att_src, att_dst);

    // K3..K5: build dst-CSR
    count_kernel<<<(GTOT + 255) / 256, 256>>>(eidx);
    const int NB = (GN + 1023) / 1024;   // 98
    scanA_kernel<<<NB, 1024>>>();
    scanC_kernel<<<NB, 1024>>>();
    fill_kernel<<<(GTOT + 255) / 256, 256>>>(eidx);

    // K6: fused softmax + aggregation + log_softmax, one warp per dst node
    gather_kernel<<<(GN * 32 + 255) / 256, 256>>>(bias, out);
}

// round 5
// speedup vs baseline: 1.1744x; 1.0960x over previous
#include <cuda_runtime.h>
#include <math.h>

// Problem constants (fixed by reference)
#define GN   100000      // nodes
#define GF   256         // in features
#define GO   64          // out features (H*C)
#define GH   8           // heads
#define GE   1600000     // edges
#define GTOT (GE + GN)   // edges + self loops
#define NEG_SLOPE 0.2f

// ---------------- static device scratch (no allocations allowed) -------------
__device__ float g_h[GN * GO];        // projected features [N,64]
__device__ float g_asrc[GN * GH];     // per-node src attention term [N,8]
__device__ float g_adst[GN * GH];     // per-node dst attention term [N,8]
__device__ int   g_count[GN];         // degree counter -> CSR cursor -> row end
__device__ int   g_rowptr[GN];        // CSR row start (by dst)
__device__ int   g_srclist[GTOT];     // CSR: src node ids grouped by dst
__device__ int   g_bsum[128];         // scan block sums
__device__ int   g_is64;              // 1 if edge_index is int64, 0 if int32

// ---------------- K0: detect edge_index dtype --------------------------------
__global__ void dtype_kernel(const void* ei) {
    if (threadIdx.x != 0 || blockIdx.x != 0) return;
    const long long* p = (const long long*)ei;
    int ok64 = 1;
    for (int i = 0; i < 64; i++) {
        long long v = p[i];
        if (v < 0 || v >= GN) { ok64 = 0; break; }
    }
    g_is64 = ok64;
}

__device__ __forceinline__ int edge_at(const void* ei, long long idx) {
    if (g_is64) return (int)((const long long*)ei)[idx];
    return ((const int*)ei)[idx];
}

// ---------------- K1: GEMM  h = x @ W^T + fused attention epilogue -----------
// 128 threads, 8x8 per thread. Column n = head*8 + c, and n0 = tn*8, so thread
// (tm,tn) holds exactly head tn for its 8 rows: a_src/a_dst are thread-local.
#define BM 128
#define BN 64
#define BK 16
__global__ void __launch_bounds__(128) gemm_kernel(const float* __restrict__ x,
                                                   const float* __restrict__ W,
                                                   const float* __restrict__ att_src,
                                                   const float* __restrict__ att_dst) {
    __shared__ float As[BK][BM + 4];
    __shared__ float Bs[BK][BN + 4];

    const int tid = threadIdx.x;          // 128 threads
    const int m_block = blockIdx.x * BM;
    const int tm = tid >> 3;              // 16 threads along M
    const int tn = tid & 7;               // 8 threads along N (== head)
    const int m0 = tm * 8;
    const int n0 = tn * 8;

    // zero the degree counters while we're here (block covers 128 node ids)
    if (m_block + tid < GN) g_count[m_block + tid] = 0;

    float acc[8][8];
#pragma unroll
    for (int i = 0; i < 8; i++)
#pragma unroll
        for (int j = 0; j < 8; j++) acc[i][j] = 0.f;

    for (int k0 = 0; k0 < GF; k0 += BK) {
#pragma unroll
        for (int i = 0; i < 4; i++) {
            int f   = tid + i * 128;
            int row = f >> 2;
            int k4  = (f & 3) << 2;
            int gm  = m_block + row;
            float4 v = make_float4(0.f, 0.f, 0.f, 0.f);
            if (gm < GN) v = *(const float4*)(x + (size_t)gm * GF + k0 + k4);
            As[k4 + 0][row] = v.x; As[k4 + 1][row] = v.y;
            As[k4 + 2][row] = v.z; As[k4 + 3][row] = v.w;
        }
#pragma unroll
        for (int i = 0; i < 2; i++) {
            int f  = tid + i * 128;
            int n  = f >> 2;
            int k4 = (f & 3) << 2;
            float4 v = *(const float4*)(W + n * GF + k0 + k4);
            Bs[k4 + 0][n] = v.x; Bs[k4 + 1][n] = v.y;
            Bs[k4 + 2][n] = v.z; Bs[k4 + 3][n] = v.w;
        }
        __syncthreads();
#pragma unroll
        for (int k = 0; k < BK; k++) {
            float a[8], b[8];
            *(float4*)&a[0] = *(const float4*)&As[k][m0];
            *(float4*)&a[4] = *(const float4*)&As[k][m0 + 4];
            *(float4*)&b[0] = *(const float4*)&Bs[k][n0];
            *(float4*)&b[4] = *(const float4*)&Bs[k][n0 + 4];
#pragma unroll
            for (int i = 0; i < 8; i++)
#pragma unroll
                for (int j = 0; j < 8; j++) acc[i][j] += a[i] * b[j];
        }
        __syncthreads();
    }

    // attention vectors for this head
    float asv[8], adv[8];
    {
        const float4* s = (const float4*)(att_src + tn * 8);
        const float4* d = (const float4*)(att_dst + tn * 8);
        float4 s0 = s[0], s1 = s[1], d0 = d[0], d1 = d[1];
        asv[0]=s0.x; asv[1]=s0.y; asv[2]=s0.z; asv[3]=s0.w;
        asv[4]=s1.x; asv[5]=s1.y; asv[6]=s1.z; asv[7]=s1.w;
        adv[0]=d0.x; adv[1]=d0.y; adv[2]=d0.z; adv[3]=d0.w;
        adv[4]=d1.x; adv[5]=d1.y; adv[6]=d1.z; adv[7]=d1.w;
    }

#pragma unroll
    for (int i = 0; i < 8; i++) {
        int gm = m_block + m0 + i;
        if (gm < GN) {
            *(float4*)(g_h + (size_t)gm * GO + n0)     =
                make_float4(acc[i][0], acc[i][1], acc[i][2], acc[i][3]);
            *(float4*)(g_h + (size_t)gm * GO + n0 + 4) =
                make_float4(acc[i][4], acc[i][5], acc[i][6], acc[i][7]);
            float rs = 0.f, rd = 0.f;
#pragma unroll
            for (int j = 0; j < 8; j++) { rs += acc[i][j] * asv[j]; rd += acc[i][j] * adv[j]; }
            g_asrc[gm * GH + tn] = rs;
            g_adst[gm * GH + tn] = rd;
        }
    }
}

// ---------------- K3: count incoming edges per dst ---------------------------
__global__ void count_kernel(const void* __restrict__ ei) {
    int i = blockIdx.x * blockDim.x + threadIdx.x;
    if (i >= GTOT) return;
    int d = (i < GE) ? edge_at(ei, (long long)GE + i) : (i - GE);
    if ((unsigned)d < (unsigned)GN)
        atomicAdd(&g_count[d], 1);
}

// ---------------- K4a/b: scan of counts -> rowptr ----------------------------
__global__ void scanA_kernel() {
    __shared__ int sh[1024];
    int t = threadIdx.x;
    int n = blockIdx.x * 1024 + t;
    sh[t] = (n < GN) ? g_count[n] : 0;
    __syncthreads();
    for (int off = 512; off > 0; off >>= 1) {
        if (t < off) sh[t] += sh[t + off];
        __syncthreads();
    }
    if (t == 0) g_bsum[blockIdx.x] = sh[0];
}
__global__ void scanC_kernel() {
    __shared__ int sh[1024];
    __shared__ int s_off;
    int t = threadIdx.x;
    sh[t] = (t < 128 && t < blockIdx.x) ? g_bsum[t] : 0;
    __syncthreads();
    for (int off = 512; off > 0; off >>= 1) {
        if (t < off) sh[t] += sh[t + off];
        __syncthreads();
    }
    if (t == 0) s_off = sh[0];
    __syncthreads();

    int n = blockIdx.x * 1024 + t;
    int v = (n < GN) ? g_count[n] : 0;
    sh[t] = v;
    __syncthreads();
    for (int off = 1; off < 1024; off <<= 1) {
        int x = (t >= off) ? sh[t - off] : 0;
        __syncthreads();
        sh[t] += x;
        __syncthreads();
    }
    if (n < GN) {
        int ex = sh[t] - v + s_off;
        g_rowptr[n] = ex;
        g_count[n]  = ex;
    }
}

// ---------------- K5: fill CSR src lists -------------------------------------
__global__ void fill_kernel(const void* __restrict__ ei) {
    int i = blockIdx.x * blockDim.x + threadIdx.x;
    if (i >= GTOT) return;
    int s, d;
    if (i < GE) { s = edge_at(ei, i); d = edge_at(ei, (long long)GE + i); }
    else        { s = d = i - GE; }
    if ((unsigned)d >= (unsigned)GN || (unsigned)s >= (unsigned)GN) return;
    int pos = atomicAdd(&g_count[d], 1);
    if ((unsigned)pos < (unsigned)GTOT) g_srclist[pos] = s;
}

// ---------------- K6: warp-per-dst gather ------------------------------------
// Lane = edge for softmax (deg>32 is ~1e-4 probability: slow path).
// Normalized alphas cached in smem; pass C = pure h-row gather + FMA.
__global__ void __launch_bounds__(256) gather_kernel(const float* __restrict__ bias,
                                                     float* __restrict__ out) {
    __shared__ float s_al[8][32][9];   // [warp][edge][head(+pad)] alpha
    __shared__ int   s_src[8][32];     // [warp][edge] src id
    __shared__ float s_mx[8][8];       // [warp][head] max      (slow path)
    __shared__ float s_iv[8][8];       // [warp][head] 1/sum    (slow path)
    const int wid  = threadIdx.x >> 5;
    const int lane = threadIdx.x & 31;
    const int n    = blockIdx.x * 8 + wid;
    if (n >= GN) return;

    const int start = g_rowptr[n];
    const int end   = g_count[n];
    const int deg   = end - start;

    float ad[8];
    {
        const float4* p = (const float4*)(g_adst + n * GH);
        float4 u0 = p[0], u1 = p[1];
        ad[0]=u0.x; ad[1]=u0.y; ad[2]=u0.z; ad[3]=u0.w;
        ad[4]=u1.x; ad[5]=u1.y; ad[6]=u1.z; ad[7]=u1.w;
    }

    // ---- chunk0 logits in registers (lane = edge) ----
    const bool have = lane < deg;
    int s0 = 0;
    float v[8];
    if (have) {
        s0 = g_srclist[start + lane];
        const float4* p = (const float4*)(g_asrc + s0 * GH);
        float4 u0 = p[0], u1 = p[1];
        float av[8] = {u0.x,u0.y,u0.z,u0.w,u1.x,u1.y,u1.z,u1.w};
#pragma unroll
        for (int h = 0; h < 8; h++) {
            float t = av[h] + ad[h];
            v[h] = t > 0.f ? t : NEG_SLOPE * t;
        }
    } else {
#pragma unroll
        for (int h = 0; h < 8; h++) v[h] = -1e30f;
    }

    // ---- max (incl. rare extra chunks) ----
    float mx[8];
#pragma unroll
    for (int h = 0; h < 8; h++) mx[h] = v[h];
    for (int i = start + 32 + lane; i < end; i += 32) {
        int s = g_srclist[i];
        const float4* p = (const float4*)(g_asrc + s * GH);
        float4 u0 = p[0], u1 = p[1];
        float av[8] = {u0.x,u0.y,u0.z,u0.w,u1.x,u1.y,u1.z,u1.w};
#pragma unroll
        for (int h = 0; h < 8; h++) {
            float t = av[h] + ad[h];
            t = t > 0.f ? t : NEG_SLOPE * t;
            mx[h] = fmaxf(mx[h], t);
        }
    }
#pragma unroll
    for (int h = 0; h < 8; h++)
#pragma unroll
        for (int off = 16; off > 0; off >>= 1)
            mx[h] = fmaxf(mx[h], __shfl_xor_sync(0xffffffffu, mx[h], off));

    // ---- sum of exp ----
    float ex[8], sm[8];
#pragma unroll
    for (int h = 0; h < 8; h++) {
        ex[h] = have ? __expf(v[h] - mx[h]) : 0.f;
        sm[h] = ex[h];
    }
    for (int i = start + 32 + lane; i < end; i += 32) {
        int s = g_srclist[i];
        const float4* p = (const float4*)(g_asrc + s * GH);
        float4 u0 = p[0], u1 = p[1];
        float av[8] = {u0.x,u0.y,u0.z,u0.w,u1.x,u1.y,u1.z,u1.w};
#pragma unroll
        for (int h = 0; h < 8; h++) {
            float t = av[h] + ad[h];
            t = t > 0.f ? t : NEG_SLOPE * t;
            sm[h] += __expf(t - mx[h]);
        }
    }
#pragma unroll
    for (int h = 0; h < 8; h++)
#pragma unroll
        for (int off = 16; off > 0; off >>= 1)
            sm[h] += __shfl_xor_sync(0xffffffffu, sm[h], off);

    float iv[8];
#pragma unroll
    for (int h = 0; h < 8; h++) iv[h] = 1.f / (sm[h] + 1e-16f);

    // ---- cache alpha + src in smem ----
    if (have) {
        s_src[wid][lane] = s0;
#pragma unroll
        for (int h = 0; h < 8; h++) s_al[wid][lane][h] = ex[h] * iv[h];
    }
    if (lane == 0) {
#pragma unroll
        for (int h = 0; h < 8; h++) { s_mx[wid][h] = mx[h]; s_iv[wid][h] = iv[h]; }
    }
    __syncwarp();

    // ---- pass C: lane handles components (2*lane, 2*lane+1); head = lane>>2 -
    const int hme = lane >> 2;
    const int m   = deg < 32 ? deg : 32;
    float acc0 = 0.f, acc1 = 0.f;
    int i = 0;
    for (; i + 4 <= m; i += 4) {
#pragma unroll
        for (int u = 0; u < 4; u++) {
            int   s = s_src[wid][i + u];
            float a = s_al[wid][i + u][hme];
            float2 hv = *(const float2*)(g_h + (size_t)s * GO + 2 * lane);
            acc0 += a * hv.x;
            acc1 += a * hv.y;
        }
    }
    for (; i < m; i++) {
        int   s = s_src[wid][i];
        float a = s_al[wid][i][hme];
        float2 hv = *(const float2*)(g_h + (size_t)s * GO + 2 * lane);
        acc0 += a * hv.x;
        acc1 += a * hv.y;
    }
    // rare slow path: edges beyond 32
    if (deg > 32) {
        float mxh = s_mx[wid][hme], ivh = s_iv[wid][hme];
        float adh = g_adst[n * GH + hme];
        for (int j = start + 32; j < end; j++) {
            int s = g_srclist[j];
            float t = g_asrc[s * GH + hme] + adh;
            t = t > 0.f ? t : NEG_SLOPE * t;
            float a = __expf(t - mxh) * ivh;
            float2 hv = *(const float2*)(g_h + (size_t)s * GO + 2 * lane);
            acc0 += a * hv.x;
            acc1 += a * hv.y;
        }
    }
    {
        float2 b = *(const float2*)(bias + 2 * lane);
        acc0 += b.x;
        acc1 += b.y;
    }

    // ---- log_softmax over 64 components ----
    float vmax = fmaxf(acc0, acc1);
#pragma unroll
    for (int off = 16; off > 0; off >>= 1)
        vmax = fmaxf(vmax, __shfl_xor_sync(0xffffffffu, vmax, off));
    float se = __expf(acc0 - vmax) + __expf(acc1 - vmax);
#pragma unroll
    for (int off = 16; off > 0; off >>= 1)
        se += __shfl_xor_sync(0xffffffffu, se, off);
    float lg = vmax + __logf(se);

    float2 o = make_float2(acc0 - lg, acc1 - lg);
    *(float2*)(out + (size_t)n * GO + 2 * lane) = o;
}

// ---------------- launcher ---------------------------------------------------
extern "C" void kernel_launch(void* const* d_in, const int* in_sizes, int n_in,
                              void* d_out, int out_size) {
    const float* x       = (const float*)d_in[0];
    const void*  eidx    = d_in[1];                 // int32 or int64, probed on device
    const float* W       = (const float*)d_in[2];
    const float* att_src = (const float*)d_in[3];
    const float* att_dst = (const float*)d_in[4];
    const float* bias    = (const float*)d_in[5];
    float*       out     = (float*)d_out;

    dtype_kernel<<<1, 32>>>(eidx);

    // GEMM + fused attention terms + counter zeroing
    gemm_kernel<<<(GN + BM - 1) / BM, 128>>>(x, W, att_src, att_dst);

    // build dst-CSR
    count_kernel<<<(GTOT + 255) / 256, 256>>>(eidx);
    const int NB = (GN + 1023) / 1024;   // 98
    scanA_kernel<<<NB, 1024>>>();
    scanC_kernel<<<NB, 1024>>>();
    fill_kernel<<<(GTOT + 255) / 256, 256>>>(eidx);

    // fused softmax + aggregation + log_softmax, one warp per dst node
    gather_kernel<<<(GN * 32 + 255) / 256, 256>>>(bias, out);
}